// round 3
// baseline (speedup 1.0000x reference)
#include <cuda_runtime.h>
#include <cuda_bf16.h>
#include <cstdint>

// Problem constants (fixed shapes from reference setup_inputs)
#define BB 8
#define SS 4096
#define DD 512
#define HH 512
#define H2 1024
#define MM (BB * SS)   // 32768

// Scratch: gh buffer [M, 2H] (128MB) and layer-1 hidden output [M, H] (64MB).
__device__ float g_gh[(long long)MM * H2];
__device__ float g_h1[(long long)MM * HH];

__device__ __forceinline__ uint32_t f2tf32(float x) {
    uint32_t r;
    asm("cvt.rna.tf32.f32 %0, %1;" : "=r"(r) : "f"(x));
    return r;
}

__device__ __forceinline__ void mma_tf32(float* c, const uint32_t* a, const uint32_t* b) {
    asm volatile(
        "mma.sync.aligned.m16n8k8.row.col.f32.tf32.tf32.f32 "
        "{%0,%1,%2,%3}, {%4,%5,%6,%7}, {%8,%9}, {%0,%1,%2,%3};"
        : "+f"(c[0]), "+f"(c[1]), "+f"(c[2]), "+f"(c[3])
        : "r"(a[0]), "r"(a[1]), "r"(a[2]), "r"(a[3]),
          "r"(b[0]), "r"(b[1]));
}

// C[M,1024] = A[M,K] * W[1024,K]^T + bias, tf32 tensor cores.
// Block tile 128x128, BK=32, 256 threads = 8 warps (2m x 4n), warp tile 64x32.
__global__ void __launch_bounds__(256) gemm_tf32(
    const float* __restrict__ A, const float* __restrict__ W,
    const float* __restrict__ bias, float* __restrict__ C, int K)
{
    __shared__ uint32_t As[128][36];   // [m][k], pad 4 -> conflict-free frags
    __shared__ uint32_t Bs[128][36];   // [n][k]

    const int tid    = threadIdx.x;
    const int wid    = tid >> 5;
    const int lane   = tid & 31;
    const int warp_m = wid >> 2;       // 0..1 -> 64 rows
    const int warp_n = wid & 3;        // 0..3 -> 32 cols
    const int bm     = blockIdx.y * 128;
    const int bn     = blockIdx.x * 128;
    const int r      = lane >> 2;      // 0..7
    const int cq     = lane & 3;       // 0..3

    float acc[4][4][4];
#pragma unroll
    for (int i = 0; i < 4; i++)
#pragma unroll
        for (int j = 0; j < 4; j++)
#pragma unroll
            for (int w = 0; w < 4; w++) acc[i][j][w] = 0.f;

    const float* Ag = A + (size_t)bm * K;
    const float* Wg = W + (size_t)bn * K;

    for (int k0 = 0; k0 < K; k0 += 32) {
        // Stage 128x32 tiles of A and W, fp32 -> tf32, coalesced float4 loads.
#pragma unroll
        for (int j = 0; j < 4; j++) {
            int idx = tid + 256 * j;
            int row = idx >> 3;
            int k4  = (idx & 7) << 2;
            float4 av = *(const float4*)(Ag + (size_t)row * K + k0 + k4);
            float4 wv = *(const float4*)(Wg + (size_t)row * K + k0 + k4);
            uint4 at, wt;
            at.x = f2tf32(av.x); at.y = f2tf32(av.y);
            at.z = f2tf32(av.z); at.w = f2tf32(av.w);
            wt.x = f2tf32(wv.x); wt.y = f2tf32(wv.y);
            wt.z = f2tf32(wv.z); wt.w = f2tf32(wv.w);
            *(uint4*)&As[row][k4] = at;
            *(uint4*)&Bs[row][k4] = wt;
        }
        __syncthreads();

#pragma unroll
        for (int ks = 0; ks < 4; ks++) {
            const int kc = ks * 8 + cq;
            uint32_t a[4][4], b[4][2];
#pragma unroll
            for (int mt = 0; mt < 4; mt++) {
                int mb = warp_m * 64 + mt * 16;
                a[mt][0] = As[mb + r][kc];
                a[mt][1] = As[mb + r + 8][kc];
                a[mt][2] = As[mb + r][kc + 4];
                a[mt][3] = As[mb + r + 8][kc + 4];
            }
#pragma unroll
            for (int nt = 0; nt < 4; nt++) {
                int nb = warp_n * 32 + nt * 8 + r;
                b[nt][0] = Bs[nb][kc];
                b[nt][1] = Bs[nb][kc + 4];
            }
#pragma unroll
            for (int mt = 0; mt < 4; mt++)
#pragma unroll
                for (int nt = 0; nt < 4; nt++)
                    mma_tf32(acc[mt][nt], a[mt], b[nt]);
        }
        __syncthreads();
    }

    // Epilogue: add bias, store fp32 (N = 1024 fixed).
#pragma unroll
    for (int mt = 0; mt < 4; mt++) {
        int row0 = bm + warp_m * 64 + mt * 16 + r;
#pragma unroll
        for (int nt = 0; nt < 4; nt++) {
            int col = bn + warp_n * 32 + nt * 8 + 2 * cq;
            float b0 = bias[col], b1 = bias[col + 1];
            float2 v0 = make_float2(acc[mt][nt][0] + b0, acc[mt][nt][1] + b1);
            float2 v1 = make_float2(acc[mt][nt][2] + b0, acc[mt][nt][3] + b1);
            *(float2*)&C[(size_t)row0 * H2 + col]       = v0;
            *(float2*)&C[(size_t)(row0 + 8) * H2 + col] = v1;
        }
    }
}

// Sequential minGRU scan. One thread per (b, h) chain.
// h_t = sigmoid(-gate)*h_{t-1} + sigmoid(gate)*g(hidden), h_0 = 0.5
// g(x) = x + 0.5 (x>=0), sigmoid(x) (x<0)
__global__ void __launch_bounds__(32) scan_kernel(
    const float* __restrict__ gh, float* __restrict__ out,
    float* __restrict__ last)
{
    const int idx = blockIdx.x * 32 + threadIdx.x;   // 0 .. B*H-1
    const int b = idx >> 9;                          // / 512
    const int h = idx & 511;

    const float* gb = gh + (size_t)b * SS * H2 + h;
    float* ob = out + (size_t)b * SS * HH + h;

    float hp = 0.5f;
#pragma unroll 4
    for (int t = 0; t < SS; ++t) {
        float gate = __ldg(gb + (size_t)t * H2);
        float hid  = __ldg(gb + (size_t)t * H2 + HH);
        float e = __expf(gate);
        float rr = __fdividef(1.f, 1.f + e);   // sigmoid(-gate)
        float z  = e * rr;                     // sigmoid(gate)
        float g  = (hid >= 0.f) ? (hid + 0.5f)
                                : __fdividef(1.f, 1.f + __expf(-hid));
        hp = fmaf(rr, hp, z * g);
        ob[(size_t)t * HH] = hp;
    }
    last[idx] = hp;
}

extern "C" void kernel_launch(void* const* d_in, const int* in_sizes, int n_in,
                              void* d_out, int out_size)
{
    const float* x  = (const float*)d_in[0];
    const float* w0 = (const float*)d_in[1];
    const float* b0 = (const float*)d_in[2];
    const float* w1 = (const float*)d_in[3];
    const float* b1 = (const float*)d_in[4];
    float* out = (float*)d_out;

    float *gh, *h1;
    cudaGetSymbolAddress((void**)&gh, g_gh);
    cudaGetSymbolAddress((void**)&h1, g_h1);

    dim3 ggrid(H2 / 128, MM / 128);   // (8, 256)

    // Layer 1: gh = x @ w0^T + b0 ; scan -> h1, last -> next_hidden[0]
    gemm_tf32<<<ggrid, 256>>>(x, w0, b0, gh, DD);
    scan_kernel<<<(BB * HH) / 32, 32>>>(gh, h1, out + (size_t)MM * HH);

    // Layer 2: gh = h1 @ w1^T + b1 ; scan -> out, last -> next_hidden[1]
    gemm_tf32<<<ggrid, 256>>>(h1, w1, b1, gh, HH);
    scan_kernel<<<(BB * HH) / 32, 32>>>(gh, out,
                                        out + (size_t)MM * HH + BB * HH);
}

// round 5
// speedup vs baseline: 2.5954x; 2.5954x over previous
#include <cuda_runtime.h>
#include <cuda_bf16.h>
#include <cstdint>

// Problem constants (fixed shapes from reference setup_inputs)
#define BB 8
#define SS 4096
#define DD 512
#define HH 512
#define H2 1024
#define MM (BB * SS)   // 32768
#define NCH 4096       // B*H chains
#define NC 16          // chunks per chain
#define CT 256         // steps per chunk

// Scratch: gh buffer [M, 2H] (128MB), layer-1 hidden output [M, H] (64MB),
// and chunk-scan summaries.
__device__ float g_gh[(long long)MM * H2];
__device__ float g_h1[(long long)MM * HH];
__device__ float g_A[NC * NCH];
__device__ float g_B[NC * NCH];
__device__ float g_Hi[NC * NCH];

__device__ __forceinline__ uint32_t f2tf32(float x) {
    uint32_t r;
    asm("cvt.rna.tf32.f32 %0, %1;" : "=r"(r) : "f"(x));
    return r;
}

__device__ __forceinline__ void mma_tf32(float* c, const uint32_t* a, const uint32_t* b) {
    asm volatile(
        "mma.sync.aligned.m16n8k8.row.col.f32.tf32.tf32.f32 "
        "{%0,%1,%2,%3}, {%4,%5,%6,%7}, {%8,%9}, {%0,%1,%2,%3};"
        : "+f"(c[0]), "+f"(c[1]), "+f"(c[2]), "+f"(c[3])
        : "r"(a[0]), "r"(a[1]), "r"(a[2]), "r"(a[3]),
          "r"(b[0]), "r"(b[1]));
}

// C[M,1024] = A[M,K] * W[1024,K]^T + bias, tf32 tensor cores.
// Block tile 128x128, BK=32, 256 threads = 8 warps (2m x 4n), warp tile 64x32.
__global__ void __launch_bounds__(256) gemm_tf32(
    const float* __restrict__ A, const float* __restrict__ W,
    const float* __restrict__ bias, float* __restrict__ C, int K)
{
    __shared__ uint32_t As[128][36];   // [m][k], pad 4 -> conflict-free frags
    __shared__ uint32_t Bs[128][36];   // [n][k]

    const int tid    = threadIdx.x;
    const int wid    = tid >> 5;
    const int lane   = tid & 31;
    const int warp_m = wid >> 2;       // 0..1 -> 64 rows
    const int warp_n = wid & 3;        // 0..3 -> 32 cols
    const int bm     = blockIdx.y * 128;
    const int bn     = blockIdx.x * 128;
    const int r      = lane >> 2;      // 0..7
    const int cq     = lane & 3;       // 0..3

    float acc[4][4][4];
#pragma unroll
    for (int i = 0; i < 4; i++)
#pragma unroll
        for (int j = 0; j < 4; j++)
#pragma unroll
            for (int w = 0; w < 4; w++) acc[i][j][w] = 0.f;

    const float* Ag = A + (size_t)bm * K;
    const float* Wg = W + (size_t)bn * K;

    for (int k0 = 0; k0 < K; k0 += 32) {
#pragma unroll
        for (int j = 0; j < 4; j++) {
            int idx = tid + 256 * j;
            int row = idx >> 3;
            int k4  = (idx & 7) << 2;
            float4 av = *(const float4*)(Ag + (size_t)row * K + k0 + k4);
            float4 wv = *(const float4*)(Wg + (size_t)row * K + k0 + k4);
            uint4 at, wt;
            at.x = f2tf32(av.x); at.y = f2tf32(av.y);
            at.z = f2tf32(av.z); at.w = f2tf32(av.w);
            wt.x = f2tf32(wv.x); wt.y = f2tf32(wv.y);
            wt.z = f2tf32(wv.z); wt.w = f2tf32(wv.w);
            *(uint4*)&As[row][k4] = at;
            *(uint4*)&Bs[row][k4] = wt;
        }
        __syncthreads();

#pragma unroll
        for (int ks = 0; ks < 4; ks++) {
            const int kc = ks * 8 + cq;
            uint32_t a[4][4], b[4][2];
#pragma unroll
            for (int mt = 0; mt < 4; mt++) {
                int mb = warp_m * 64 + mt * 16;
                a[mt][0] = As[mb + r][kc];
                a[mt][1] = As[mb + r + 8][kc];
                a[mt][2] = As[mb + r][kc + 4];
                a[mt][3] = As[mb + r + 8][kc + 4];
            }
#pragma unroll
            for (int nt = 0; nt < 4; nt++) {
                int nb = warp_n * 32 + nt * 8 + r;
                b[nt][0] = Bs[nb][kc];
                b[nt][1] = Bs[nb][kc + 4];
            }
#pragma unroll
            for (int mt = 0; mt < 4; mt++)
#pragma unroll
                for (int nt = 0; nt < 4; nt++)
                    mma_tf32(acc[mt][nt], a[mt], b[nt]);
        }
        __syncthreads();
    }

#pragma unroll
    for (int mt = 0; mt < 4; mt++) {
        int row0 = bm + warp_m * 64 + mt * 16 + r;
#pragma unroll
        for (int nt = 0; nt < 4; nt++) {
            int col = bn + warp_n * 32 + nt * 8 + 2 * cq;
            float b0 = bias[col], b1 = bias[col + 1];
            float2 v0 = make_float2(acc[mt][nt][0] + b0, acc[mt][nt][1] + b1);
            float2 v1 = make_float2(acc[mt][nt][2] + b0, acc[mt][nt][3] + b1);
            *(float2*)&C[(size_t)row0 * H2 + col]       = v0;
            *(float2*)&C[(size_t)(row0 + 8) * H2 + col] = v1;
        }
    }
}

// Elementwise recurrence terms from gh:
//   r = sigmoid(-gate), v = sigmoid(gate)*g(hidden)
//   g(x) = x + 0.5 (x>=0), sigmoid(x) (x<0)
__device__ __forceinline__ void rv_from_gh(float gate, float hid,
                                           float& rr, float& v) {
    float e = __expf(gate);
    rr = __fdividef(1.f, 1.f + e);        // sigmoid(-gate)
    float z = e * rr;                     // sigmoid(gate)
    float g = (hid >= 0.f) ? (hid + 0.5f)
                           : __fdividef(1.f, 1.f + __expf(-hid));
    v = z * g;
}

// Pass 1: per (chain, chunk) local affine composition (A = prod r, B = scan).
// idx: h in bits [0,9), chunk in [9,13), b in [13,16). 65536 threads.
__global__ void __launch_bounds__(256) scan_pass1(
    const float* __restrict__ gh, float* __restrict__ Aout,
    float* __restrict__ Bout)
{
    const int idx = blockIdx.x * 256 + threadIdx.x;
    const int h = idx & 511;
    const int c = (idx >> 9) & (NC - 1);
    const int b = idx >> 13;

    const float* gb = gh + ((size_t)b * SS + (size_t)c * CT) * H2 + h;
    float A = 1.f, Bv = 0.f;
#pragma unroll 4
    for (int t = 0; t < CT; ++t) {
        float gate = __ldg(gb + (size_t)t * H2);
        float hid  = __ldg(gb + (size_t)t * H2 + HH);
        float rr, v;
        rv_from_gh(gate, hid, rr, v);
        A *= rr;
        Bv = fmaf(rr, Bv, v);
    }
    const int chain = b * 512 + h;
    Aout[c * NCH + chain] = A;
    Bout[c * NCH + chain] = Bv;
}

// Pass 2: sequential prefix over the NC chunk summaries per chain.
// Emits per-chunk initial h and the final hidden state (= next_hidden).
__global__ void __launch_bounds__(256) scan_pass2(
    const float* __restrict__ A, const float* __restrict__ B,
    float* __restrict__ Hinit, float* __restrict__ last)
{
    const int chain = blockIdx.x * 256 + threadIdx.x;   // 0..4095
    float h = 0.5f;
#pragma unroll
    for (int c = 0; c < NC; ++c) {
        Hinit[c * NCH + chain] = h;
        h = fmaf(A[c * NCH + chain], h, B[c * NCH + chain]);
    }
    last[chain] = h;
}

// Pass 3: replay each chunk from its correct initial h, write outputs.
__global__ void __launch_bounds__(256) scan_pass3(
    const float* __restrict__ gh, const float* __restrict__ Hinit,
    float* __restrict__ out)
{
    const int idx = blockIdx.x * 256 + threadIdx.x;
    const int h = idx & 511;
    const int c = (idx >> 9) & (NC - 1);
    const int b = idx >> 13;

    const float* gb = gh + ((size_t)b * SS + (size_t)c * CT) * H2 + h;
    float* ob = out + ((size_t)b * SS + (size_t)c * CT) * HH + h;

    float hp = Hinit[c * NCH + b * 512 + h];
#pragma unroll 4
    for (int t = 0; t < CT; ++t) {
        float gate = __ldg(gb + (size_t)t * H2);
        float hid  = __ldg(gb + (size_t)t * H2 + HH);
        float rr, v;
        rv_from_gh(gate, hid, rr, v);
        hp = fmaf(rr, hp, v);
        ob[(size_t)t * HH] = hp;
    }
}

extern "C" void kernel_launch(void* const* d_in, const int* in_sizes, int n_in,
                              void* d_out, int out_size)
{
    const float* x  = (const float*)d_in[0];
    const float* w0 = (const float*)d_in[1];
    const float* b0 = (const float*)d_in[2];
    const float* w1 = (const float*)d_in[3];
    const float* b1 = (const float*)d_in[4];
    float* out = (float*)d_out;

    float *gh, *h1, *Ab, *Bb, *Hi;
    cudaGetSymbolAddress((void**)&gh, g_gh);
    cudaGetSymbolAddress((void**)&h1, g_h1);
    cudaGetSymbolAddress((void**)&Ab, g_A);
    cudaGetSymbolAddress((void**)&Bb, g_B);
    cudaGetSymbolAddress((void**)&Hi, g_Hi);

    dim3 ggrid(H2 / 128, MM / 128);   // (8, 256)
    const int sgrid = (NCH * NC) / 256;  // 256 blocks for pass1/pass3

    float* last0 = out + (size_t)MM * HH;            // next_hidden[0]
    float* last1 = last0 + (size_t)BB * HH;          // next_hidden[1]

    // Layer 1
    gemm_tf32<<<ggrid, 256>>>(x, w0, b0, gh, DD);
    scan_pass1<<<sgrid, 256>>>(gh, Ab, Bb);
    scan_pass2<<<NCH / 256, 256>>>(Ab, Bb, Hi, last0);
    scan_pass3<<<sgrid, 256>>>(gh, Hi, h1);

    // Layer 2
    gemm_tf32<<<ggrid, 256>>>(h1, w1, b1, gh, HH);
    scan_pass1<<<sgrid, 256>>>(gh, Ab, Bb);
    scan_pass2<<<NCH / 256, 256>>>(Ab, Bb, Hi, last1);
    scan_pass3<<<sgrid, 256>>>(gh, Hi, out);
}